// round 14
// baseline (speedup 1.0000x reference)
#include <cuda_runtime.h>
#include <cuda_fp16.h>
#include <math.h>
#include <stdint.h>

#define B_    2
#define NQ    2048
#define NCTX  2048
#define QDIM  1024
#define INNER 512
#define HEADS 8
#define DHEAD 64

// Q prescale: (1/sqrt(64)) * log2(e)  -> QK logits land in log2 domain
#define QSCALE 0.18033688011112042f

// -------- one big fp16 scratch buffer (offsets in elements) --------
#define O_X  0ull
#define O_C  4194304ull
#define O_WQ 8388608ull
#define O_WK 8912896ull
#define O_WV 9437184ull
#define O_WO 9961472ull
#define O_Q  10485760ull
#define O_K  12582912ull
#define O_V  14680064ull
#define O_A  16777216ull
#define BUF_TOTAL 18874368ull

__device__ __align__(16) __half g_buf[BUF_TOTAL];

// ============================================================
// helpers
// ============================================================
__device__ __forceinline__ uint32_t smem_u32(const void* p) {
    uint32_t a;
    asm("{ .reg .u64 t; cvta.to.shared.u64 t, %1; cvt.u32.u64 %0, t; }" : "=r"(a) : "l"(p));
    return a;
}
__device__ __forceinline__ void ldm_x4(uint32_t* r, uint32_t a) {
    asm volatile("ldmatrix.sync.aligned.m8n8.x4.shared.b16 {%0,%1,%2,%3}, [%4];"
                 : "=r"(r[0]), "=r"(r[1]), "=r"(r[2]), "=r"(r[3]) : "r"(a));
}
__device__ __forceinline__ void ldm_x4t(uint32_t* r, uint32_t a) {
    asm volatile("ldmatrix.sync.aligned.m8n8.x4.trans.shared.b16 {%0,%1,%2,%3}, [%4];"
                 : "=r"(r[0]), "=r"(r[1]), "=r"(r[2]), "=r"(r[3]) : "r"(a));
}
__device__ __forceinline__ void ldm_x2t(uint32_t* r, uint32_t a) {
    asm volatile("ldmatrix.sync.aligned.m8n8.x2.trans.shared.b16 {%0,%1}, [%2];"
                 : "=r"(r[0]), "=r"(r[1]) : "r"(a));
}
__device__ __forceinline__ void mma_h(float* c, const uint32_t* a, const uint32_t* b) {
    asm volatile(
        "mma.sync.aligned.m16n8k16.row.col.f32.f16.f16.f32 "
        "{%0,%1,%2,%3}, {%4,%5,%6,%7}, {%8,%9}, {%0,%1,%2,%3};"
        : "+f"(c[0]), "+f"(c[1]), "+f"(c[2]), "+f"(c[3])
        : "r"(a[0]), "r"(a[1]), "r"(a[2]), "r"(a[3]), "r"(b[0]), "r"(b[1]));
}
__device__ __forceinline__ uint32_t pack2h(float x, float y) {
    __half2 h = __floats2half2_rn(x, y);
    return *(uint32_t*)&h;
}
__device__ __forceinline__ uint32_t ex2h2(uint32_t a) {
    uint32_t d;
    asm volatile("ex2.approx.f16x2 %0, %1;" : "=r"(d) : "r"(a));
    return d;
}
__device__ __forceinline__ void cpa16(uint32_t s, const void* g) {
    asm volatile("cp.async.cg.shared.global [%0], [%1], 16;" :: "r"(s), "l"(g));
}
__device__ __forceinline__ void cpa_commit() {
    asm volatile("cp.async.commit_group;" ::: "memory");
}

// ============================================================
// merged presplit: one launch converts x, ctx, Wq, Wk, Wv, Wo
// ============================================================
__global__ __launch_bounds__(256) void pres_all(const float4* __restrict__ x,
                                                const float4* __restrict__ ctx,
                                                const float4* __restrict__ Wq,
                                                const float4* __restrict__ Wk,
                                                const float4* __restrict__ Wv,
                                                const float4* __restrict__ Wo) {
    int i = blockIdx.x * 256 + threadIdx.x;   // 0 .. 2621439
    const float4* in;
    int idx;
    if (i < 1048576) {
        in = x; idx = i;
    } else if (i < 2097152) {
        in = ctx; idx = i - 1048576;
    } else {
        int j = i - 2097152;
        int wsel = j >> 17;
        idx = j & 131071;
        in = (wsel == 0) ? Wq : (wsel == 1) ? Wk : (wsel == 2) ? Wv : Wo;
    }
    float4 v = in[idx];
    ((uint2*)g_buf)[i] = make_uint2(pack2h(v.x, v.y), pack2h(v.z, v.w));
}

// ============================================================
// GEMM core v3 (unchanged from R13): 128x128 tile, K-chunks of 64,
// 3-stage cp.async, batched fragment loads. 8 warps (4m x 2n).
// ============================================================
#define GS_A 0
#define GS_W 18432
#define G_STAGE 35840
#define G_SMEM (3 * G_STAGE)

__device__ __forceinline__ void gemm_stage_load(uint32_t st, const __half* A,
                                                const __half* W,
                                                int K, int N, int m0, int n0, int k0, int t) {
#pragma unroll
    for (int i = t; i < 1024; i += 256) {
        int row = i >> 3, ch = i & 7;
        size_t go = (size_t)(m0 + row) * K + k0 + ch * 8;
        cpa16(st + GS_A + row * 144 + ch * 16, A + go);
    }
#pragma unroll
    for (int i = t; i < 1024; i += 256) {
        int row = i >> 4, ch = i & 15;
        size_t go = (size_t)(k0 + row) * N + n0 + ch * 8;
        cpa16(st + GS_W + row * 272 + ch * 16, W + go);
    }
}

// MODE 0: fp32 out + bias. MODE 2: fp16 out (Ch) * scale.
template <int MODE>
__device__ void gemm_core(const __half* __restrict__ A, const __half* __restrict__ W,
                          const float* __restrict__ bias, float* __restrict__ Cf,
                          __half* __restrict__ Ch, float scale,
                          int N, int K, int m0, int n0, char* sm) {
    const uint32_t sb = smem_u32(sm);
    const int t   = threadIdx.x;
    const int wid = t >> 5;
    const int l   = t & 31;
    const int wm  = (wid & 3) * 32;
    const int wn  = (wid >> 2) * 64;

    float acc[2][8][4] = {};

    const int a_moff = (l & 7) + ((l >> 3) & 1) * 8;
    const int a_koff = (l >> 4) * 8;
    const int b_koff = ((l >> 3) & 1) * 8 + (l & 7);
    const int b_noff = (l >> 4) * 8;

    const int nch = K >> 6;   // chunks of 64
    gemm_stage_load(sb, A, W, K, N, m0, n0, 0, t);
    cpa_commit();
    if (nch > 1) {
        gemm_stage_load(sb + G_STAGE, A, W, K, N, m0, n0, 64, t);
        cpa_commit();
    }

    for (int ch = 0; ch < nch; ++ch) {
        if (ch + 1 < nch) {
            asm volatile("cp.async.wait_group 1;" ::: "memory");
        } else {
            asm volatile("cp.async.wait_group 0;" ::: "memory");
        }
        __syncthreads();
        if (ch + 2 < nch) {
            gemm_stage_load(sb + ((ch + 2) % 3) * G_STAGE, A, W,
                            K, N, m0, n0, (ch + 2) << 6, t);
            cpa_commit();
        }
        const uint32_t st = sb + (ch % 3) * G_STAGE;
#pragma unroll
        for (int ks = 0; ks < 4; ++ks) {
            uint32_t ah[2][4];
#pragma unroll
            for (int mt = 0; mt < 2; ++mt) {
                uint32_t ao = st + GS_A + (uint32_t)(wm + mt * 16 + a_moff) * 144u
                            + (uint32_t)(ks * 16 + a_koff) * 2u;
                ldm_x4(ah[mt], ao);
            }
            uint32_t wf[4][4];
#pragma unroll
            for (int np = 0; np < 4; ++np) {
                uint32_t bo = st + GS_W + (uint32_t)(ks * 16 + b_koff) * 272u
                            + (uint32_t)(wn + np * 16 + b_noff) * 2u;
                ldm_x4t(wf[np], bo);
            }
#pragma unroll
            for (int np = 0; np < 4; ++np)
#pragma unroll
                for (int mt = 0; mt < 2; ++mt) {
                    mma_h(acc[mt][2 * np],     ah[mt], wf[np]);
                    mma_h(acc[mt][2 * np + 1], ah[mt], wf[np] + 2);
                }
        }
    }

#pragma unroll
    for (int mt = 0; mt < 2; ++mt) {
#pragma unroll
        for (int nt = 0; nt < 8; ++nt) {
            int row = m0 + wm + mt * 16 + (l >> 2);
            int col = n0 + wn + nt * 8 + (l & 3) * 2;
            if (MODE == 0) {
                float b0 = bias[col], b1 = bias[col + 1];
                *(float2*)(Cf + (size_t)row * N + col) =
                    make_float2(acc[mt][nt][0] + b0, acc[mt][nt][1] + b1);
                *(float2*)(Cf + (size_t)(row + 8) * N + col) =
                    make_float2(acc[mt][nt][2] + b0, acc[mt][nt][3] + b1);
            } else {
                *(uint32_t*)(Ch + (size_t)row * N + col) =
                    pack2h(acc[mt][nt][0] * scale, acc[mt][nt][1] * scale);
                *(uint32_t*)(Ch + (size_t)(row + 8) * N + col) =
                    pack2h(acc[mt][nt][2] * scale, acc[mt][nt][3] * scale);
            }
        }
    }
}

__global__ __launch_bounds__(256, 2) void qkv_kernel() {
    extern __shared__ char sm[];
    int which = blockIdx.x >> 2;
    int n0 = (blockIdx.x & 3) * 128;
    int m0 = blockIdx.y * 128;
    if (which == 0) {
        gemm_core<2>(g_buf + O_X, g_buf + O_WQ, nullptr, nullptr,
                     g_buf + O_Q, QSCALE, INNER, QDIM, m0, n0, sm);
    } else if (which == 1) {
        gemm_core<2>(g_buf + O_C, g_buf + O_WK, nullptr, nullptr,
                     g_buf + O_K, 1.0f, INNER, QDIM, m0, n0, sm);
    } else {
        gemm_core<2>(g_buf + O_C, g_buf + O_WV, nullptr, nullptr,
                     g_buf + O_V, 1.0f, INNER, QDIM, m0, n0, sm);
    }
}

__global__ __launch_bounds__(256, 2) void proj_kernel(const float* __restrict__ bo,
                                                      float* __restrict__ out) {
    extern __shared__ char sm[];
    gemm_core<0>(g_buf + O_A, g_buf + O_WO, bo, out, nullptr, 1.0f,
                 QDIM, INNER, blockIdx.y * 128, blockIdx.x * 128, sm);
}

// ============================================================
// Flash attention v10: 256-thread CTA (8 warps), warp = 16 q rows.
// 4 warps/SMSP with 2 CTAs/SM -> better tensor-pipe fill during
// softmax phases. KV tiles 64, 4-stage cp.async, batched frag loads.
// Softmax: Q prescaled to log2 domain, P = ex2.approx.f16x2,
// row sums via ones-column mma (V padding col 64).
// smem: QH 0 (18432), stages at 18432: 4 x (K 9216 | V 9216)
// ============================================================
#define AQ_H  0
#define AKV0  18432
#define AS_K  0
#define AS_V  9216
#define A_STAGE 18432
#define A_SMEM (AKV0 + 4 * A_STAGE)   // 92160

__device__ __forceinline__ void attn_stage_load(uint32_t st, const __half* kg,
                                                const __half* vg,
                                                size_t base, int jt, int t) {
#pragma unroll
    for (int i = t; i < 512; i += 256) {
        int row = i >> 3, ch = i & 7;
        size_t go = base + (size_t)(jt * 64 + row) * INNER + ch * 8;
        uint32_t so = st + row * 144 + ch * 16;
        cpa16(so + AS_K, kg + go);
        cpa16(so + AS_V, vg + go);
    }
}

__global__ __launch_bounds__(256, 2) void attn_kernel() {
    extern __shared__ char sm[];
    const uint32_t sb = smem_u32(sm);
    const int t = threadIdx.x;
    const int w = t >> 5;   // 0..7
    const int l = t & 31;
    const int qt = blockIdx.x;
    const int h  = blockIdx.y;
    const int b  = blockIdx.z;

    const __half* q_g = g_buf + O_Q;
    const __half* k_g = g_buf + O_K;
    const __half* v_g = g_buf + O_V;

    const size_t qbase = ((size_t)b * NQ + (size_t)qt * 128) * INNER + h * DHEAD;
    const size_t kvbase = (size_t)b * NCTX * INNER + h * DHEAD;

    // ---- ones column into V padding (col 64; cols 65-71 zero), 4 stages ----
    {
        int s = t >> 6, row = t & 63;   // 256 threads cover 4 stages x 64 rows
        *(uint4*)(sm + AKV0 + s * A_STAGE + AS_V + row * 144 + 128) =
            make_uint4(0x3C00u, 0u, 0u, 0u);
    }

    // ---- Q prologue ----
#pragma unroll
    for (int i = t; i < 1024; i += 256) {
        int row = i >> 3, ch = i & 7;
        size_t go = qbase + (size_t)row * INNER + ch * 8;
        *(uint4*)(sm + AQ_H + row * 144 + ch * 16) = *(const uint4*)(q_g + go);
    }

    const int a_moff = (l & 7) + ((l >> 3) & 1) * 8;
    const int a_koff = (l >> 4) * 8;
    const int kb_noff = ((l >> 4) * 8) + (l & 7);
    const int kb_koff = ((l >> 3) & 1) * 8;
    const int vb_koff = ((l >> 3) & 1) * 8 + (l & 7);
    const int vb_noff = (l >> 4) * 8;
    const int ob_koff = (l & 7) + ((l >> 3) & 1) * 8;  // ones-col ldm.x2

    __syncthreads();

    // Q fragments: 1 m-tile x 4 k-steps, resident
    uint32_t qh[4][4];
#pragma unroll
    for (int ks = 0; ks < 4; ++ks) {
        uint32_t ao = sb + AQ_H + (uint32_t)(w * 16 + a_moff) * 144u
                    + (uint32_t)(ks * 16 + a_koff) * 2u;
        ldm_x4(qh[ks], ao);
    }

    float o[8][4] = {};
    float osum[4] = {};

    const int NT = NCTX / 64;  // 32
    attn_stage_load(sb + AKV0, k_g, v_g, kvbase, 0, t);
    cpa_commit();
    attn_stage_load(sb + AKV0 + A_STAGE, k_g, v_g, kvbase, 1, t);
    cpa_commit();
    attn_stage_load(sb + AKV0 + 2 * A_STAGE, k_g, v_g, kvbase, 2, t);
    cpa_commit();

    for (int jt = 0; jt < NT; ++jt) {
        if (jt + 2 < NT) {
            asm volatile("cp.async.wait_group 2;" ::: "memory");
        } else if (jt + 1 < NT) {
            asm volatile("cp.async.wait_group 1;" ::: "memory");
        } else {
            asm volatile("cp.async.wait_group 0;" ::: "memory");
        }
        __syncthreads();
        if (jt + 3 < NT) {
            attn_stage_load(sb + AKV0 + ((jt + 3) & 3) * A_STAGE, k_g, v_g,
                            kvbase, jt + 3, t);
            cpa_commit();
        }
        const uint32_t st = sb + AKV0 + (jt & 3) * A_STAGE;

        // ---- S = Q K^T (log2-domain logits), batched K frags per ks ----
        float s[8][4] = {};
#pragma unroll
        for (int ks = 0; ks < 4; ++ks) {
            uint32_t kf[4][4];
#pragma unroll
            for (int np = 0; np < 4; ++np) {
                uint32_t ko = st + AS_K + (uint32_t)(np * 16 + kb_noff) * 144u
                            + (uint32_t)(ks * 16 + kb_koff) * 2u;
                ldm_x4(kf[np], ko);
            }
#pragma unroll
            for (int np = 0; np < 4; ++np) {
                mma_h(s[2 * np],     qh[ks], kf[np]);
                mma_h(s[2 * np + 1], qh[ks], kf[np] + 2);
            }
        }

        // ---- P = 2^s (fp16x2), O += P V, osum += P * ones ----
#pragma unroll
        for (int ks = 0; ks < 4; ++ks) {
            uint32_t vf[4][4];
#pragma unroll
            for (int np = 0; np < 4; ++np) {
                uint32_t vo = st + AS_V + (uint32_t)(ks * 16 + vb_koff) * 144u
                            + (uint32_t)(np * 16 + vb_noff) * 2u;
                ldm_x4t(vf[np], vo);
            }
            uint32_t bones[2];
            ldm_x2t(bones, st + AS_V + (uint32_t)(ks * 16 + ob_koff) * 144u + 128u);
            uint32_t pr[4];
#pragma unroll
            for (int r = 0; r < 4; ++r) {
                const float* c = s[2 * ks + (r >> 1)];
                pr[r] = ex2h2(pack2h(c[(r & 1) * 2], c[(r & 1) * 2 + 1]));
            }
#pragma unroll
            for (int np = 0; np < 4; ++np) {
                mma_h(o[2 * np],     pr, vf[np]);
                mma_h(o[2 * np + 1], pr, vf[np] + 2);
            }
            mma_h(osum, pr, bones);
        }
    }

    // ---- epilogue: row sums in col-64 accumulators of lanes (l&3)==0 ----
    float l0 = __shfl_sync(0xffffffffu, osum[0], l & ~3);
    float l1 = __shfl_sync(0xffffffffu, osum[2], l & ~3);
    float inv0 = 1.0f / l0;
    float inv1 = 1.0f / l1;

    int row = qt * 128 + w * 16 + (l >> 2);
    __half* ag = g_buf + O_A;
    size_t obase = ((size_t)b * NQ + row) * INNER + h * DHEAD;
#pragma unroll
    for (int nt = 0; nt < 8; ++nt) {
        int col = nt * 8 + (l & 3) * 2;
        *(uint32_t*)(ag + obase + col) = pack2h(o[nt][0] * inv0, o[nt][1] * inv0);
        *(uint32_t*)(ag + obase + (size_t)8 * INNER + col) =
            pack2h(o[nt][2] * inv1, o[nt][3] * inv1);
    }
}

// ============================================================
extern "C" void kernel_launch(void* const* d_in, const int* in_sizes, int n_in,
                              void* d_out, int out_size) {
    const float* x   = (const float*)d_in[0];
    const float* ctx = (const float*)d_in[1];
    const float* Wq  = (const float*)d_in[2];
    const float* Wk  = (const float*)d_in[3];
    const float* Wv  = (const float*)d_in[4];
    const float* Wo  = (const float*)d_in[5];
    const float* bo  = (const float*)d_in[6];
    float* out = (float*)d_out;

    pres_all<<<10240, 256>>>((const float4*)x, (const float4*)ctx,
                             (const float4*)Wq, (const float4*)Wk,
                             (const float4*)Wv, (const float4*)Wo);

    cudaFuncSetAttribute(qkv_kernel,  cudaFuncAttributeMaxDynamicSharedMemorySize, G_SMEM);
    cudaFuncSetAttribute(proj_kernel, cudaFuncAttributeMaxDynamicSharedMemorySize, G_SMEM);
    cudaFuncSetAttribute(attn_kernel, cudaFuncAttributeMaxDynamicSharedMemorySize, A_SMEM);

    qkv_kernel<<<dim3(12, 32), 256, G_SMEM>>>();
    attn_kernel<<<dim3(NQ / 128, HEADS, B_), 256, A_SMEM>>>();
    proj_kernel<<<dim3(QDIM / 128, 32), 256, G_SMEM>>>(bo, out);
}

// round 15
// speedup vs baseline: 1.0132x; 1.0132x over previous
#include <cuda_runtime.h>
#include <cuda_fp16.h>
#include <math.h>
#include <stdint.h>

#define B_    2
#define NQ    2048
#define NCTX  2048
#define QDIM  1024
#define INNER 512
#define HEADS 8
#define DHEAD 64

// Q prescale: (1/sqrt(64)) * log2(e)  -> QK logits land in log2 domain
#define QSCALE 0.18033688011112042f

// -------- one big fp16 scratch buffer (offsets in elements) --------
#define O_X  0ull
#define O_C  4194304ull
#define O_WQ 8388608ull
#define O_WK 8912896ull
#define O_WV 9437184ull
#define O_WO 9961472ull
#define O_Q  10485760ull
#define O_K  12582912ull
#define O_V  14680064ull
#define O_A  16777216ull
#define BUF_TOTAL 18874368ull

__device__ __align__(16) __half g_buf[BUF_TOTAL];

// ============================================================
// helpers
// ============================================================
__device__ __forceinline__ uint32_t smem_u32(const void* p) {
    uint32_t a;
    asm("{ .reg .u64 t; cvta.to.shared.u64 t, %1; cvt.u32.u64 %0, t; }" : "=r"(a) : "l"(p));
    return a;
}
__device__ __forceinline__ void ldm_x4(uint32_t* r, uint32_t a) {
    asm volatile("ldmatrix.sync.aligned.m8n8.x4.shared.b16 {%0,%1,%2,%3}, [%4];"
                 : "=r"(r[0]), "=r"(r[1]), "=r"(r[2]), "=r"(r[3]) : "r"(a));
}
__device__ __forceinline__ void ldm_x4t(uint32_t* r, uint32_t a) {
    asm volatile("ldmatrix.sync.aligned.m8n8.x4.trans.shared.b16 {%0,%1,%2,%3}, [%4];"
                 : "=r"(r[0]), "=r"(r[1]), "=r"(r[2]), "=r"(r[3]) : "r"(a));
}
__device__ __forceinline__ void ldm_x2t(uint32_t* r, uint32_t a) {
    asm volatile("ldmatrix.sync.aligned.m8n8.x2.trans.shared.b16 {%0,%1}, [%2];"
                 : "=r"(r[0]), "=r"(r[1]) : "r"(a));
}
__device__ __forceinline__ void mma_h(float* c, const uint32_t* a, const uint32_t* b) {
    asm volatile(
        "mma.sync.aligned.m16n8k16.row.col.f32.f16.f16.f32 "
        "{%0,%1,%2,%3}, {%4,%5,%6,%7}, {%8,%9}, {%0,%1,%2,%3};"
        : "+f"(c[0]), "+f"(c[1]), "+f"(c[2]), "+f"(c[3])
        : "r"(a[0]), "r"(a[1]), "r"(a[2]), "r"(a[3]), "r"(b[0]), "r"(b[1]));
}
__device__ __forceinline__ uint32_t pack2h(float x, float y) {
    __half2 h = __floats2half2_rn(x, y);
    return *(uint32_t*)&h;
}
__device__ __forceinline__ uint32_t ex2h2(uint32_t a) {
    uint32_t d;
    asm volatile("ex2.approx.f16x2 %0, %1;" : "=r"(d) : "r"(a));
    return d;
}
__device__ __forceinline__ void cpa16(uint32_t s, const void* g) {
    asm volatile("cp.async.cg.shared.global [%0], [%1], 16;" :: "r"(s), "l"(g));
}
__device__ __forceinline__ void cpa_commit() {
    asm volatile("cp.async.commit_group;" ::: "memory");
}

// ============================================================
// merged presplit: one launch converts x, ctx, Wq, Wk, Wv, Wo
// ============================================================
__global__ __launch_bounds__(256) void pres_all(const float4* __restrict__ x,
                                                const float4* __restrict__ ctx,
                                                const float4* __restrict__ Wq,
                                                const float4* __restrict__ Wk,
                                                const float4* __restrict__ Wv,
                                                const float4* __restrict__ Wo) {
    int i = blockIdx.x * 256 + threadIdx.x;   // 0 .. 2621439
    const float4* in;
    int idx;
    if (i < 1048576) {
        in = x; idx = i;
    } else if (i < 2097152) {
        in = ctx; idx = i - 1048576;
    } else {
        int j = i - 2097152;
        int wsel = j >> 17;
        idx = j & 131071;
        in = (wsel == 0) ? Wq : (wsel == 1) ? Wk : (wsel == 2) ? Wv : Wo;
    }
    float4 v = in[idx];
    ((uint2*)g_buf)[i] = make_uint2(pack2h(v.x, v.y), pack2h(v.z, v.w));
}

// ============================================================
// GEMM core v4: 128 x (NP*32) tile, K-chunks of 64, 3-stage
// cp.async, batched fragment loads. 8 warps (4m x 2n).
// NP = n-tiles (16 cols each) per warp: 4 -> 128-wide CTA tile,
// 2 -> 64-wide CTA tile (finer wave packing).
// ============================================================
#define GS_A 0
#define GS_W 18432

template <int NP>
__device__ __forceinline__ void gemm_stage_load(uint32_t st, const __half* A,
                                                const __half* W,
                                                int K, int N, int m0, int n0, int k0, int t) {
    const int PW = NP * 64 + 16;
#pragma unroll
    for (int i = t; i < 1024; i += 256) {
        int row = i >> 3, ch = i & 7;
        size_t go = (size_t)(m0 + row) * K + k0 + ch * 8;
        cpa16(st + GS_A + row * 144 + ch * 16, A + go);
    }
#pragma unroll
    for (int i = t; i < 256 * NP; i += 256) {
        int row = i / (NP * 4), ch = i % (NP * 4);
        size_t go = (size_t)(k0 + row) * N + n0 + ch * 8;
        cpa16(st + GS_W + row * PW + ch * 16, W + go);
    }
}

// MODE 0: fp32 out + bias. MODE 2: fp16 out (Ch) * scale.
template <int MODE, int NP>
__device__ void gemm_core(const __half* __restrict__ A, const __half* __restrict__ W,
                          const float* __restrict__ bias, float* __restrict__ Cf,
                          __half* __restrict__ Ch, float scale,
                          int N, int K, int m0, int n0, char* sm) {
    const int PW = NP * 64 + 16;
    const int STAGE = 18432 + 64 * PW;
    const uint32_t sb = smem_u32(sm);
    const int t   = threadIdx.x;
    const int wid = t >> 5;
    const int l   = t & 31;
    const int wm  = (wid & 3) * 32;
    const int wn  = (wid >> 2) * (NP * 16);

    float acc[2][2 * NP][4] = {};

    const int a_moff = (l & 7) + ((l >> 3) & 1) * 8;
    const int a_koff = (l >> 4) * 8;
    const int b_koff = ((l >> 3) & 1) * 8 + (l & 7);
    const int b_noff = (l >> 4) * 8;

    const int nch = K >> 6;   // chunks of 64
    gemm_stage_load<NP>(sb, A, W, K, N, m0, n0, 0, t);
    cpa_commit();
    if (nch > 1) {
        gemm_stage_load<NP>(sb + STAGE, A, W, K, N, m0, n0, 64, t);
        cpa_commit();
    }

    for (int ch = 0; ch < nch; ++ch) {
        if (ch + 1 < nch) {
            asm volatile("cp.async.wait_group 1;" ::: "memory");
        } else {
            asm volatile("cp.async.wait_group 0;" ::: "memory");
        }
        __syncthreads();
        if (ch + 2 < nch) {
            gemm_stage_load<NP>(sb + ((ch + 2) % 3) * STAGE, A, W,
                                K, N, m0, n0, (ch + 2) << 6, t);
            cpa_commit();
        }
        const uint32_t st = sb + (ch % 3) * STAGE;
#pragma unroll
        for (int ks = 0; ks < 4; ++ks) {
            uint32_t ah[2][4];
#pragma unroll
            for (int mt = 0; mt < 2; ++mt) {
                uint32_t ao = st + GS_A + (uint32_t)(wm + mt * 16 + a_moff) * 144u
                            + (uint32_t)(ks * 16 + a_koff) * 2u;
                ldm_x4(ah[mt], ao);
            }
            uint32_t wf[NP][4];
#pragma unroll
            for (int np = 0; np < NP; ++np) {
                uint32_t bo = st + GS_W + (uint32_t)(ks * 16 + b_koff) * PW
                            + (uint32_t)(wn + np * 16 + b_noff) * 2u;
                ldm_x4t(wf[np], bo);
            }
#pragma unroll
            for (int np = 0; np < NP; ++np)
#pragma unroll
                for (int mt = 0; mt < 2; ++mt) {
                    mma_h(acc[mt][2 * np],     ah[mt], wf[np]);
                    mma_h(acc[mt][2 * np + 1], ah[mt], wf[np] + 2);
                }
        }
    }

#pragma unroll
    for (int mt = 0; mt < 2; ++mt) {
#pragma unroll
        for (int nt = 0; nt < 2 * NP; ++nt) {
            int row = m0 + wm + mt * 16 + (l >> 2);
            int col = n0 + wn + nt * 8 + (l & 3) * 2;
            if (MODE == 0) {
                float b0 = bias[col], b1 = bias[col + 1];
                *(float2*)(Cf + (size_t)row * N + col) =
                    make_float2(acc[mt][nt][0] + b0, acc[mt][nt][1] + b1);
                *(float2*)(Cf + (size_t)(row + 8) * N + col) =
                    make_float2(acc[mt][nt][2] + b0, acc[mt][nt][3] + b1);
            } else {
                *(uint32_t*)(Ch + (size_t)row * N + col) =
                    pack2h(acc[mt][nt][0] * scale, acc[mt][nt][1] * scale);
                *(uint32_t*)(Ch + (size_t)(row + 8) * N + col) =
                    pack2h(acc[mt][nt][2] * scale, acc[mt][nt][3] * scale);
            }
        }
    }
}

#define G_SMEM_QKV  (3 * (18432 + 64 * (2 * 64 + 16)))   // NP=2: 82944
#define G_SMEM_PROJ (3 * (18432 + 64 * (4 * 64 + 16)))   // NP=4: 107520

// qkv with NP=2 (64-wide tiles): 3 gemms x 8 n-blocks x 32 m-blocks = 768 CTAs
__global__ __launch_bounds__(256, 2) void qkv_kernel() {
    extern __shared__ char sm[];
    int which = blockIdx.x >> 3;
    int n0 = (blockIdx.x & 7) * 64;
    int m0 = blockIdx.y * 128;
    if (which == 0) {
        gemm_core<2, 2>(g_buf + O_X, g_buf + O_WQ, nullptr, nullptr,
                        g_buf + O_Q, QSCALE, INNER, QDIM, m0, n0, sm);
    } else if (which == 1) {
        gemm_core<2, 2>(g_buf + O_C, g_buf + O_WK, nullptr, nullptr,
                        g_buf + O_K, 1.0f, INNER, QDIM, m0, n0, sm);
    } else {
        gemm_core<2, 2>(g_buf + O_C, g_buf + O_WV, nullptr, nullptr,
                        g_buf + O_V, 1.0f, INNER, QDIM, m0, n0, sm);
    }
}

__global__ __launch_bounds__(256, 2) void proj_kernel(const float* __restrict__ bo,
                                                      float* __restrict__ out) {
    extern __shared__ char sm[];
    gemm_core<0, 4>(g_buf + O_A, g_buf + O_WO, bo, out, nullptr, 1.0f,
                    QDIM, INNER, blockIdx.y * 128, blockIdx.x * 128, sm);
}

// ============================================================
// Flash attention (R13 config): 128-thread CTA (4 warps),
// warp = 32 q rows. KV tiles 64, 4-stage cp.async, batched frag loads.
// Softmax: Q prescaled to log2 domain, P = ex2.approx.f16x2,
// row sums via ones-column mma (V padding col 64).
// smem: QH 0 (18432), stages at 18432: 4 x (K 9216 | V 9216)
// ============================================================
#define AQ_H  0
#define AKV0  18432
#define AS_K  0
#define AS_V  9216
#define A_STAGE 18432
#define A_SMEM (AKV0 + 4 * A_STAGE)   // 92160

__device__ __forceinline__ void attn_stage_load(uint32_t st, const __half* kg,
                                                const __half* vg,
                                                size_t base, int jt, int t) {
#pragma unroll
    for (int i = t; i < 512; i += 128) {
        int row = i >> 3, ch = i & 7;
        size_t go = base + (size_t)(jt * 64 + row) * INNER + ch * 8;
        uint32_t so = st + row * 144 + ch * 16;
        cpa16(so + AS_K, kg + go);
        cpa16(so + AS_V, vg + go);
    }
}

__global__ __launch_bounds__(128, 2) void attn_kernel() {
    extern __shared__ char sm[];
    const uint32_t sb = smem_u32(sm);
    const int t = threadIdx.x;
    const int w = t >> 5;   // 0..3
    const int l = t & 31;
    const int qt = blockIdx.x;
    const int h  = blockIdx.y;
    const int b  = blockIdx.z;

    const __half* q_g = g_buf + O_Q;
    const __half* k_g = g_buf + O_K;
    const __half* v_g = g_buf + O_V;

    const size_t qbase = ((size_t)b * NQ + (size_t)qt * 128) * INNER + h * DHEAD;
    const size_t kvbase = (size_t)b * NCTX * INNER + h * DHEAD;

    // ---- ones column into V padding (col 64; cols 65-71 zero), 4 stages ----
#pragma unroll
    for (int i = t; i < 256; i += 128) {
        int s = i >> 6, row = i & 63;
        *(uint4*)(sm + AKV0 + s * A_STAGE + AS_V + row * 144 + 128) =
            make_uint4(0x3C00u, 0u, 0u, 0u);
    }

    // ---- Q prologue ----
#pragma unroll
    for (int i = t; i < 1024; i += 128) {
        int row = i >> 3, ch = i & 7;
        size_t go = qbase + (size_t)row * INNER + ch * 8;
        *(uint4*)(sm + AQ_H + row * 144 + ch * 16) = *(const uint4*)(q_g + go);
    }

    const int a_moff = (l & 7) + ((l >> 3) & 1) * 8;
    const int a_koff = (l >> 4) * 8;
    const int kb_noff = ((l >> 4) * 8) + (l & 7);
    const int kb_koff = ((l >> 3) & 1) * 8;
    const int vb_koff = ((l >> 3) & 1) * 8 + (l & 7);
    const int vb_noff = (l >> 4) * 8;
    const int ob_koff = (l & 7) + ((l >> 3) & 1) * 8;  // ones-col ldm.x2

    __syncthreads();

    // Q fragments: 2 m-tiles x 4 k-steps, resident
    uint32_t qh[2][4][4];
#pragma unroll
    for (int mt = 0; mt < 2; ++mt)
#pragma unroll
        for (int ks = 0; ks < 4; ++ks) {
            uint32_t ao = sb + AQ_H + (uint32_t)(w * 32 + mt * 16 + a_moff) * 144u
                        + (uint32_t)(ks * 16 + a_koff) * 2u;
            ldm_x4(qh[mt][ks], ao);
        }

    float o0[8][4] = {}, o1[8][4] = {};
    float osum0[4] = {}, osum1[4] = {};

    const int NT = NCTX / 64;  // 32
    attn_stage_load(sb + AKV0, k_g, v_g, kvbase, 0, t);
    cpa_commit();
    attn_stage_load(sb + AKV0 + A_STAGE, k_g, v_g, kvbase, 1, t);
    cpa_commit();
    attn_stage_load(sb + AKV0 + 2 * A_STAGE, k_g, v_g, kvbase, 2, t);
    cpa_commit();

    for (int jt = 0; jt < NT; ++jt) {
        if (jt + 2 < NT) {
            asm volatile("cp.async.wait_group 2;" ::: "memory");
        } else if (jt + 1 < NT) {
            asm volatile("cp.async.wait_group 1;" ::: "memory");
        } else {
            asm volatile("cp.async.wait_group 0;" ::: "memory");
        }
        __syncthreads();
        if (jt + 3 < NT) {
            attn_stage_load(sb + AKV0 + ((jt + 3) & 3) * A_STAGE, k_g, v_g,
                            kvbase, jt + 3, t);
            cpa_commit();
        }
        const uint32_t st = sb + AKV0 + (jt & 3) * A_STAGE;

        // ---- S = Q K^T (log2-domain logits), batched K frags per ks ----
        float s0[8][4] = {}, s1[8][4] = {};
#pragma unroll
        for (int ks = 0; ks < 4; ++ks) {
            uint32_t kf[4][4];
#pragma unroll
            for (int np = 0; np < 4; ++np) {
                uint32_t ko = st + AS_K + (uint32_t)(np * 16 + kb_noff) * 144u
                            + (uint32_t)(ks * 16 + kb_koff) * 2u;
                ldm_x4(kf[np], ko);
            }
#pragma unroll
            for (int np = 0; np < 4; ++np) {
                mma_h(s0[2 * np],     qh[0][ks], kf[np]);
                mma_h(s0[2 * np + 1], qh[0][ks], kf[np] + 2);
                mma_h(s1[2 * np],     qh[1][ks], kf[np]);
                mma_h(s1[2 * np + 1], qh[1][ks], kf[np] + 2);
            }
        }

        // ---- P = 2^s (fp16x2), O += P V, osum += P * ones ----
#pragma unroll
        for (int ks = 0; ks < 4; ++ks) {
            uint32_t vf[4][4];
#pragma unroll
            for (int np = 0; np < 4; ++np) {
                uint32_t vo = st + AS_V + (uint32_t)(ks * 16 + vb_koff) * 144u
                            + (uint32_t)(np * 16 + vb_noff) * 2u;
                ldm_x4t(vf[np], vo);
            }
            uint32_t bones[2];
            ldm_x2t(bones, st + AS_V + (uint32_t)(ks * 16 + ob_koff) * 144u + 128u);
            uint32_t pr0[4], pr1[4];
#pragma unroll
            for (int r = 0; r < 4; ++r) {
                const float* c0 = s0[2 * ks + (r >> 1)];
                const float* c1 = s1[2 * ks + (r >> 1)];
                pr0[r] = ex2h2(pack2h(c0[(r & 1) * 2], c0[(r & 1) * 2 + 1]));
                pr1[r] = ex2h2(pack2h(c1[(r & 1) * 2], c1[(r & 1) * 2 + 1]));
            }
#pragma unroll
            for (int np = 0; np < 4; ++np) {
                mma_h(o0[2 * np],     pr0, vf[np]);
                mma_h(o0[2 * np + 1], pr0, vf[np] + 2);
                mma_h(o1[2 * np],     pr1, vf[np]);
                mma_h(o1[2 * np + 1], pr1, vf[np] + 2);
            }
            mma_h(osum0, pr0, bones);
            mma_h(osum1, pr1, bones);
        }
    }

    // ---- epilogue: row sums in col-64 accumulators of lanes (l&3)==0 ----
    float l00 = __shfl_sync(0xffffffffu, osum0[0], l & ~3);
    float l01 = __shfl_sync(0xffffffffu, osum0[2], l & ~3);
    float l10 = __shfl_sync(0xffffffffu, osum1[0], l & ~3);
    float l11 = __shfl_sync(0xffffffffu, osum1[2], l & ~3);
    float i00 = 1.0f / l00, i01 = 1.0f / l01;
    float i10 = 1.0f / l10, i11 = 1.0f / l11;

    int row = qt * 128 + w * 32 + (l >> 2);
    __half* ag = g_buf + O_A;
    size_t ob0 = ((size_t)b * NQ + row) * INNER + h * DHEAD;
    size_t ob1 = ((size_t)b * NQ + row + 16) * INNER + h * DHEAD;
#pragma unroll
    for (int nt = 0; nt < 8; ++nt) {
        int col = nt * 8 + (l & 3) * 2;
        *(uint32_t*)(ag + ob0 + col) = pack2h(o0[nt][0] * i00, o0[nt][1] * i00);
        *(uint32_t*)(ag + ob0 + (size_t)8 * INNER + col) =
            pack2h(o0[nt][2] * i01, o0[nt][3] * i01);
        *(uint32_t*)(ag + ob1 + col) = pack2h(o1[nt][0] * i10, o1[nt][1] * i10);
        *(uint32_t*)(ag + ob1 + (size_t)8 * INNER + col) =
            pack2h(o1[nt][2] * i11, o1[nt][3] * i11);
    }
}

// ============================================================
extern "C" void kernel_launch(void* const* d_in, const int* in_sizes, int n_in,
                              void* d_out, int out_size) {
    const float* x   = (const float*)d_in[0];
    const float* ctx = (const float*)d_in[1];
    const float* Wq  = (const float*)d_in[2];
    const float* Wk  = (const float*)d_in[3];
    const float* Wv  = (const float*)d_in[4];
    const float* Wo  = (const float*)d_in[5];
    const float* bo  = (const float*)d_in[6];
    float* out = (float*)d_out;

    pres_all<<<10240, 256>>>((const float4*)x, (const float4*)ctx,
                             (const float4*)Wq, (const float4*)Wk,
                             (const float4*)Wv, (const float4*)Wo);

    cudaFuncSetAttribute(qkv_kernel,  cudaFuncAttributeMaxDynamicSharedMemorySize, G_SMEM_QKV);
    cudaFuncSetAttribute(proj_kernel, cudaFuncAttributeMaxDynamicSharedMemorySize, G_SMEM_PROJ);
    cudaFuncSetAttribute(attn_kernel, cudaFuncAttributeMaxDynamicSharedMemorySize, A_SMEM);

    qkv_kernel<<<dim3(24, 32), 256, G_SMEM_QKV>>>();
    attn_kernel<<<dim3(NQ / 128, HEADS, B_), 128, A_SMEM>>>();
    proj_kernel<<<dim3(QDIM / 128, 32), 256, G_SMEM_PROJ>>>(bo, out);
}

// round 16
// speedup vs baseline: 1.0427x; 1.0292x over previous
#include <cuda_runtime.h>
#include <cuda_fp16.h>
#include <math.h>
#include <stdint.h>

#define B_    2
#define NQ    2048
#define NCTX  2048
#define QDIM  1024
#define INNER 512
#define HEADS 8
#define DHEAD 64

// Q prescale: (1/sqrt(64)) * log2(e)  -> QK logits land in log2 domain
#define QSCALE 0.18033688011112042f

// -------- one big fp16 scratch buffer (offsets in elements) --------
#define O_X  0ull
#define O_C  4194304ull
#define O_WQ 8388608ull
#define O_WK 8912896ull
#define O_WV 9437184ull
#define O_WO 9961472ull
#define O_Q  10485760ull
#define O_K  12582912ull
#define O_V  14680064ull
#define O_A  16777216ull
#define BUF_TOTAL 18874368ull

__device__ __align__(16) __half g_buf[BUF_TOTAL];

// ============================================================
// helpers
// ============================================================
__device__ __forceinline__ uint32_t smem_u32(const void* p) {
    uint32_t a;
    asm("{ .reg .u64 t; cvta.to.shared.u64 t, %1; cvt.u32.u64 %0, t; }" : "=r"(a) : "l"(p));
    return a;
}
__device__ __forceinline__ void ldm_x4(uint32_t* r, uint32_t a) {
    asm volatile("ldmatrix.sync.aligned.m8n8.x4.shared.b16 {%0,%1,%2,%3}, [%4];"
                 : "=r"(r[0]), "=r"(r[1]), "=r"(r[2]), "=r"(r[3]) : "r"(a));
}
__device__ __forceinline__ void ldm_x4t(uint32_t* r, uint32_t a) {
    asm volatile("ldmatrix.sync.aligned.m8n8.x4.trans.shared.b16 {%0,%1,%2,%3}, [%4];"
                 : "=r"(r[0]), "=r"(r[1]), "=r"(r[2]), "=r"(r[3]) : "r"(a));
}
__device__ __forceinline__ void ldm_x2t(uint32_t* r, uint32_t a) {
    asm volatile("ldmatrix.sync.aligned.m8n8.x2.trans.shared.b16 {%0,%1}, [%2];"
                 : "=r"(r[0]), "=r"(r[1]) : "r"(a));
}
__device__ __forceinline__ void mma_h(float* c, const uint32_t* a, const uint32_t* b) {
    asm volatile(
        "mma.sync.aligned.m16n8k16.row.col.f32.f16.f16.f32 "
        "{%0,%1,%2,%3}, {%4,%5,%6,%7}, {%8,%9}, {%0,%1,%2,%3};"
        : "+f"(c[0]), "+f"(c[1]), "+f"(c[2]), "+f"(c[3])
        : "r"(a[0]), "r"(a[1]), "r"(a[2]), "r"(a[3]), "r"(b[0]), "r"(b[1]));
}
__device__ __forceinline__ uint32_t pack2h(float x, float y) {
    __half2 h = __floats2half2_rn(x, y);
    return *(uint32_t*)&h;
}
__device__ __forceinline__ uint32_t ex2h2(uint32_t a) {
    uint32_t d;
    asm volatile("ex2.approx.f16x2 %0, %1;" : "=r"(d) : "r"(a));
    return d;
}
__device__ __forceinline__ void cpa16(uint32_t s, const void* g) {
    asm volatile("cp.async.cg.shared.global [%0], [%1], 16;" :: "r"(s), "l"(g));
}
__device__ __forceinline__ void cpa_commit() {
    asm volatile("cp.async.commit_group;" ::: "memory");
}

// ============================================================
// merged presplit: one launch converts x, ctx, Wq, Wk, Wv, Wo
// ============================================================
__global__ __launch_bounds__(256) void pres_all(const float4* __restrict__ x,
                                                const float4* __restrict__ ctx,
                                                const float4* __restrict__ Wq,
                                                const float4* __restrict__ Wk,
                                                const float4* __restrict__ Wv,
                                                const float4* __restrict__ Wo) {
    int i = blockIdx.x * 256 + threadIdx.x;   // 0 .. 2621439
    const float4* in;
    int idx;
    if (i < 1048576) {
        in = x; idx = i;
    } else if (i < 2097152) {
        in = ctx; idx = i - 1048576;
    } else {
        int j = i - 2097152;
        int wsel = j >> 17;
        idx = j & 131071;
        in = (wsel == 0) ? Wq : (wsel == 1) ? Wk : (wsel == 2) ? Wv : Wo;
    }
    float4 v = in[idx];
    ((uint2*)g_buf)[i] = make_uint2(pack2h(v.x, v.y), pack2h(v.z, v.w));
}

// ============================================================
// GEMM core v5: 128 x (NP*32) tile, K-chunks of 64, NST-stage
// cp.async pipeline, batched fragment loads. 8 warps (4m x 2n).
// NP=4: 128-wide tile; NP=2: 64-wide tile (for 3 CTAs/SM).
// ============================================================
#define GS_A 0
#define GS_W 18432

template <int NP>
__device__ __forceinline__ void gemm_stage_load(uint32_t st, const __half* A,
                                                const __half* W,
                                                int K, int N, int m0, int n0, int k0, int t) {
    const int PW = NP * 64 + 16;
#pragma unroll
    for (int i = t; i < 1024; i += 256) {
        int row = i >> 3, ch = i & 7;
        size_t go = (size_t)(m0 + row) * K + k0 + ch * 8;
        cpa16(st + GS_A + row * 144 + ch * 16, A + go);
    }
#pragma unroll
    for (int i = t; i < 256 * NP; i += 256) {
        int row = i / (NP * 4), ch = i % (NP * 4);
        size_t go = (size_t)(k0 + row) * N + n0 + ch * 8;
        cpa16(st + GS_W + row * PW + ch * 16, W + go);
    }
}

// MODE 0: fp32 out + bias. MODE 2: fp16 out (Ch) * scale.
template <int MODE, int NP, int NST>
__device__ void gemm_core(const __half* __restrict__ A, const __half* __restrict__ W,
                          const float* __restrict__ bias, float* __restrict__ Cf,
                          __half* __restrict__ Ch, float scale,
                          int N, int K, int m0, int n0, char* sm) {
    const int PW = NP * 64 + 16;
    const int STAGE = 18432 + 64 * PW;
    const uint32_t sb = smem_u32(sm);
    const int t   = threadIdx.x;
    const int wid = t >> 5;
    const int l   = t & 31;
    const int wm  = (wid & 3) * 32;
    const int wn  = (wid >> 2) * (NP * 16);

    float acc[2][2 * NP][4] = {};

    const int a_moff = (l & 7) + ((l >> 3) & 1) * 8;
    const int a_koff = (l >> 4) * 8;
    const int b_koff = ((l >> 3) & 1) * 8 + (l & 7);
    const int b_noff = (l >> 4) * 8;

    const int nch = K >> 6;   // chunks of 64

    gemm_stage_load<NP>(sb, A, W, K, N, m0, n0, 0, t);
    cpa_commit();
    if (NST == 3 && nch > 1) {
        gemm_stage_load<NP>(sb + STAGE, A, W, K, N, m0, n0, 64, t);
        cpa_commit();
    }

    for (int ch = 0; ch < nch; ++ch) {
        if (NST == 3) {
            if (ch + 1 < nch) {
                asm volatile("cp.async.wait_group 1;" ::: "memory");
            } else {
                asm volatile("cp.async.wait_group 0;" ::: "memory");
            }
            __syncthreads();
            if (ch + 2 < nch) {
                gemm_stage_load<NP>(sb + ((ch + 2) % 3) * STAGE, A, W,
                                    K, N, m0, n0, (ch + 2) << 6, t);
                cpa_commit();
            }
        } else {
            asm volatile("cp.async.wait_group 0;" ::: "memory");
            __syncthreads();
            if (ch + 1 < nch) {
                gemm_stage_load<NP>(sb + ((ch + 1) & 1) * STAGE, A, W,
                                    K, N, m0, n0, (ch + 1) << 6, t);
                cpa_commit();
            }
        }
        const uint32_t st = sb + (NST == 3 ? (ch % 3) : (ch & 1)) * STAGE;
#pragma unroll
        for (int ks = 0; ks < 4; ++ks) {
            uint32_t ah[2][4];
#pragma unroll
            for (int mt = 0; mt < 2; ++mt) {
                uint32_t ao = st + GS_A + (uint32_t)(wm + mt * 16 + a_moff) * 144u
                            + (uint32_t)(ks * 16 + a_koff) * 2u;
                ldm_x4(ah[mt], ao);
            }
            uint32_t wf[NP][4];
#pragma unroll
            for (int np = 0; np < NP; ++np) {
                uint32_t bo = st + GS_W + (uint32_t)(ks * 16 + b_koff) * PW
                            + (uint32_t)(wn + np * 16 + b_noff) * 2u;
                ldm_x4t(wf[np], bo);
            }
#pragma unroll
            for (int np = 0; np < NP; ++np)
#pragma unroll
                for (int mt = 0; mt < 2; ++mt) {
                    mma_h(acc[mt][2 * np],     ah[mt], wf[np]);
                    mma_h(acc[mt][2 * np + 1], ah[mt], wf[np] + 2);
                }
        }
    }

#pragma unroll
    for (int mt = 0; mt < 2; ++mt) {
#pragma unroll
        for (int nt = 0; nt < 2 * NP; ++nt) {
            int row = m0 + wm + mt * 16 + (l >> 2);
            int col = n0 + wn + nt * 8 + (l & 3) * 2;
            if (MODE == 0) {
                float b0 = bias[col], b1 = bias[col + 1];
                *(float2*)(Cf + (size_t)row * N + col) =
                    make_float2(acc[mt][nt][0] + b0, acc[mt][nt][1] + b1);
                *(float2*)(Cf + (size_t)(row + 8) * N + col) =
                    make_float2(acc[mt][nt][2] + b0, acc[mt][nt][3] + b1);
            } else {
                *(uint32_t*)(Ch + (size_t)row * N + col) =
                    pack2h(acc[mt][nt][0] * scale, acc[mt][nt][1] * scale);
                *(uint32_t*)(Ch + (size_t)(row + 8) * N + col) =
                    pack2h(acc[mt][nt][2] * scale, acc[mt][nt][3] * scale);
            }
        }
    }
}

#define G_SMEM_QKV  (2 * (18432 + 64 * (2 * 64 + 16)))   // NP=2, 2-stage: 55296
#define G_SMEM_PROJ (3 * (18432 + 64 * (4 * 64 + 16)))   // NP=4, 3-stage: 107520

// qkv: NP=2 (64-wide tiles), 2-stage, 3 CTAs/SM target. 768 CTAs.
__global__ __launch_bounds__(256, 3) void qkv_kernel() {
    extern __shared__ char sm[];
    int which = blockIdx.x >> 3;
    int n0 = (blockIdx.x & 7) * 64;
    int m0 = blockIdx.y * 128;
    if (which == 0) {
        gemm_core<2, 2, 2>(g_buf + O_X, g_buf + O_WQ, nullptr, nullptr,
                           g_buf + O_Q, QSCALE, INNER, QDIM, m0, n0, sm);
    } else if (which == 1) {
        gemm_core<2, 2, 2>(g_buf + O_C, g_buf + O_WK, nullptr, nullptr,
                           g_buf + O_K, 1.0f, INNER, QDIM, m0, n0, sm);
    } else {
        gemm_core<2, 2, 2>(g_buf + O_C, g_buf + O_WV, nullptr, nullptr,
                           g_buf + O_V, 1.0f, INNER, QDIM, m0, n0, sm);
    }
}

__global__ __launch_bounds__(256, 2) void proj_kernel(const float* __restrict__ bo,
                                                      float* __restrict__ out) {
    extern __shared__ char sm[];
    gemm_core<0, 4, 3>(g_buf + O_A, g_buf + O_WO, bo, out, nullptr, 1.0f,
                       QDIM, INNER, blockIdx.y * 128, blockIdx.x * 128, sm);
}

// ============================================================
// Flash attention (R13 config, unchanged): 128-thread CTA (4 warps),
// warp = 32 q rows. KV tiles 64, 4-stage cp.async, batched frag loads.
// Softmax: Q prescaled to log2 domain, P = ex2.approx.f16x2,
// row sums via ones-column mma (V padding col 64).
// ============================================================
#define AQ_H  0
#define AKV0  18432
#define AS_K  0
#define AS_V  9216
#define A_STAGE 18432
#define A_SMEM (AKV0 + 4 * A_STAGE)   // 92160

__device__ __forceinline__ void attn_stage_load(uint32_t st, const __half* kg,
                                                const __half* vg,
                                                size_t base, int jt, int t) {
#pragma unroll
    for (int i = t; i < 512; i += 128) {
        int row = i >> 3, ch = i & 7;
        size_t go = base + (size_t)(jt * 64 + row) * INNER + ch * 8;
        uint32_t so = st + row * 144 + ch * 16;
        cpa16(so + AS_K, kg + go);
        cpa16(so + AS_V, vg + go);
    }
}

__global__ __launch_bounds__(128, 2) void attn_kernel() {
    extern __shared__ char sm[];
    const uint32_t sb = smem_u32(sm);
    const int t = threadIdx.x;
    const int w = t >> 5;   // 0..3
    const int l = t & 31;
    const int qt = blockIdx.x;
    const int h  = blockIdx.y;
    const int b  = blockIdx.z;

    const __half* q_g = g_buf + O_Q;
    const __half* k_g = g_buf + O_K;
    const __half* v_g = g_buf + O_V;

    const size_t qbase = ((size_t)b * NQ + (size_t)qt * 128) * INNER + h * DHEAD;
    const size_t kvbase = (size_t)b * NCTX * INNER + h * DHEAD;

    // ---- ones column into V padding (col 64; cols 65-71 zero), 4 stages ----
#pragma unroll
    for (int i = t; i < 256; i += 128) {
        int s = i >> 6, row = i & 63;
        *(uint4*)(sm + AKV0 + s * A_STAGE + AS_V + row * 144 + 128) =
            make_uint4(0x3C00u, 0u, 0u, 0u);
    }

    // ---- Q prologue ----
#pragma unroll
    for (int i = t; i < 1024; i += 128) {
        int row = i >> 3, ch = i & 7;
        size_t go = qbase + (size_t)row * INNER + ch * 8;
        *(uint4*)(sm + AQ_H + row * 144 + ch * 16) = *(const uint4*)(q_g + go);
    }

    const int a_moff = (l & 7) + ((l >> 3) & 1) * 8;
    const int a_koff = (l >> 4) * 8;
    const int kb_noff = ((l >> 4) * 8) + (l & 7);
    const int kb_koff = ((l >> 3) & 1) * 8;
    const int vb_koff = ((l >> 3) & 1) * 8 + (l & 7);
    const int vb_noff = (l >> 4) * 8;
    const int ob_koff = (l & 7) + ((l >> 3) & 1) * 8;  // ones-col ldm.x2

    __syncthreads();

    // Q fragments: 2 m-tiles x 4 k-steps, resident
    uint32_t qh[2][4][4];
#pragma unroll
    for (int mt = 0; mt < 2; ++mt)
#pragma unroll
        for (int ks = 0; ks < 4; ++ks) {
            uint32_t ao = sb + AQ_H + (uint32_t)(w * 32 + mt * 16 + a_moff) * 144u
                        + (uint32_t)(ks * 16 + a_koff) * 2u;
            ldm_x4(qh[mt][ks], ao);
        }

    float o0[8][4] = {}, o1[8][4] = {};
    float osum0[4] = {}, osum1[4] = {};

    const int NT = NCTX / 64;  // 32
    attn_stage_load(sb + AKV0, k_g, v_g, kvbase, 0, t);
    cpa_commit();
    attn_stage_load(sb + AKV0 + A_STAGE, k_g, v_g, kvbase, 1, t);
    cpa_commit();
    attn_stage_load(sb + AKV0 + 2 * A_STAGE, k_g, v_g, kvbase, 2, t);
    cpa_commit();

    for (int jt = 0; jt < NT; ++jt) {
        if (jt + 2 < NT) {
            asm volatile("cp.async.wait_group 2;" ::: "memory");
        } else if (jt + 1 < NT) {
            asm volatile("cp.async.wait_group 1;" ::: "memory");
        } else {
            asm volatile("cp.async.wait_group 0;" ::: "memory");
        }
        __syncthreads();
        if (jt + 3 < NT) {
            attn_stage_load(sb + AKV0 + ((jt + 3) & 3) * A_STAGE, k_g, v_g,
                            kvbase, jt + 3, t);
            cpa_commit();
        }
        const uint32_t st = sb + AKV0 + (jt & 3) * A_STAGE;

        // ---- S = Q K^T (log2-domain logits), batched K frags per ks ----
        float s0[8][4] = {}, s1[8][4] = {};
#pragma unroll
        for (int ks = 0; ks < 4; ++ks) {
            uint32_t kf[4][4];
#pragma unroll
            for (int np = 0; np < 4; ++np) {
                uint32_t ko = st + AS_K + (uint32_t)(np * 16 + kb_noff) * 144u
                            + (uint32_t)(ks * 16 + kb_koff) * 2u;
                ldm_x4(kf[np], ko);
            }
#pragma unroll
            for (int np = 0; np < 4; ++np) {
                mma_h(s0[2 * np],     qh[0][ks], kf[np]);
                mma_h(s0[2 * np + 1], qh[0][ks], kf[np] + 2);
                mma_h(s1[2 * np],     qh[1][ks], kf[np]);
                mma_h(s1[2 * np + 1], qh[1][ks], kf[np] + 2);
            }
        }

        // ---- P = 2^s (fp16x2), O += P V, osum += P * ones ----
#pragma unroll
        for (int ks = 0; ks < 4; ++ks) {
            uint32_t vf[4][4];
#pragma unroll
            for (int np = 0; np < 4; ++np) {
                uint32_t vo = st + AS_V + (uint32_t)(ks * 16 + vb_koff) * 144u
                            + (uint32_t)(np * 16 + vb_noff) * 2u;
                ldm_x4t(vf[np], vo);
            }
            uint32_t bones[2];
            ldm_x2t(bones, st + AS_V + (uint32_t)(ks * 16 + ob_koff) * 144u + 128u);
            uint32_t pr0[4], pr1[4];
#pragma unroll
            for (int r = 0; r < 4; ++r) {
                const float* c0 = s0[2 * ks + (r >> 1)];
                const float* c1 = s1[2 * ks + (r >> 1)];
                pr0[r] = ex2h2(pack2h(c0[(r & 1) * 2], c0[(r & 1) * 2 + 1]));
                pr1[r] = ex2h2(pack2h(c1[(r & 1) * 2], c1[(r & 1) * 2 + 1]));
            }
#pragma unroll
            for (int np = 0; np < 4; ++np) {
                mma_h(o0[2 * np],     pr0, vf[np]);
                mma_h(o0[2 * np + 1], pr0, vf[np] + 2);
                mma_h(o1[2 * np],     pr1, vf[np]);
                mma_h(o1[2 * np + 1], pr1, vf[np] + 2);
            }
            mma_h(osum0, pr0, bones);
            mma_h(osum1, pr1, bones);
        }
    }

    // ---- epilogue: row sums in col-64 accumulators of lanes (l&3)==0 ----
    float l00 = __shfl_sync(0xffffffffu, osum0[0], l & ~3);
    float l01 = __shfl_sync(0xffffffffu, osum0[2], l & ~3);
    float l10 = __shfl_sync(0xffffffffu, osum1[0], l & ~3);
    float l11 = __shfl_sync(0xffffffffu, osum1[2], l & ~3);
    float i00 = 1.0f / l00, i01 = 1.0f / l01;
    float i10 = 1.0f / l10, i11 = 1.0f / l11;

    int row = qt * 128 + w * 32 + (l >> 2);
    __half* ag = g_buf + O_A;
    size_t ob0 = ((size_t)b * NQ + row) * INNER + h * DHEAD;
    size_t ob1 = ((size_t)b * NQ + row + 16) * INNER + h * DHEAD;
#pragma unroll
    for (int nt = 0; nt < 8; ++nt) {
        int col = nt * 8 + (l & 3) * 2;
        *(uint32_t*)(ag + ob0 + col) = pack2h(o0[nt][0] * i00, o0[nt][1] * i00);
        *(uint32_t*)(ag + ob0 + (size_t)8 * INNER + col) =
            pack2h(o0[nt][2] * i01, o0[nt][3] * i01);
        *(uint32_t*)(ag + ob1 + col) = pack2h(o1[nt][0] * i10, o1[nt][1] * i10);
        *(uint32_t*)(ag + ob1 + (size_t)8 * INNER + col) =
            pack2h(o1[nt][2] * i11, o1[nt][3] * i11);
    }
}

// ============================================================
extern "C" void kernel_launch(void* const* d_in, const int* in_sizes, int n_in,
                              void* d_out, int out_size) {
    const float* x   = (const float*)d_in[0];
    const float* ctx = (const float*)d_in[1];
    const float* Wq  = (const float*)d_in[2];
    const float* Wk  = (const float*)d_in[3];
    const float* Wv  = (const float*)d_in[4];
    const float* Wo  = (const float*)d_in[5];
    const float* bo  = (const float*)d_in[6];
    float* out = (float*)d_out;

    pres_all<<<10240, 256>>>((const float4*)x, (const float4*)ctx,
                             (const float4*)Wq, (const float4*)Wk,
                             (const float4*)Wv, (const float4*)Wo);

    cudaFuncSetAttribute(qkv_kernel,  cudaFuncAttributeMaxDynamicSharedMemorySize, G_SMEM_QKV);
    cudaFuncSetAttribute(proj_kernel, cudaFuncAttributeMaxDynamicSharedMemorySize, G_SMEM_PROJ);
    cudaFuncSetAttribute(attn_kernel, cudaFuncAttributeMaxDynamicSharedMemorySize, A_SMEM);

    qkv_kernel<<<dim3(24, 32), 256, G_SMEM_QKV>>>();
    attn_kernel<<<dim3(NQ / 128, HEADS, B_), 128, A_SMEM>>>();
    proj_kernel<<<dim3(QDIM / 128, 32), 256, G_SMEM_PROJ>>>(bo, out);
}